// round 5
// baseline (speedup 1.0000x reference)
#include <cuda_runtime.h>
#include <cuda_bf16.h>

// LoRALayerNorm fused single kernel.
// out = layernorm(x) * scale + shift, scale/shift = lowrank diag * 2.0
// x [2,4096,8192] fp32. Blocks 0..31 build g_scale/g_shift (256 elems each),
// then flag-arrive; every block does one row (512 thr x 4 float4), gating on
// the flag only before the epilogue (gate load issued early -> hidden).

#define RANK 4
#define SCALING 2.0f
#define EPS 1e-5f
#define MAX_N 8192
#define PROD_BLOCKS 32
#define LN_T 512
#define LN_ITER 4

__device__ float g_scale[MAX_N];
__device__ float g_shift[MAX_N];
__device__ unsigned g_done = 0;   // monotonic across replays; >=32 means open

__global__ __launch_bounds__(LN_T, 2)
void fused_kernel(const float* __restrict__ x,
                  const float* __restrict__ As, const float* __restrict__ Bs,
                  const float* __restrict__ Ah, const float* __restrict__ Bh,
                  float* __restrict__ out, int N) {
    const int tid = threadIdx.x;
    const int bid = blockIdx.x;

    // ---- producer phase: first 32 blocks build scale/shift chunks ----
    if (bid < PROD_BLOCKS) {
        if (tid < 256) {
            const int i = bid * 256 + tid;
            float4 a = *(const float4*)(As + i * RANK);
            float s = a.x * Bs[i] + a.y * Bs[N + i]
                    + a.z * Bs[2 * N + i] + a.w * Bs[3 * N + i];
            float4 h = *(const float4*)(Ah + i * RANK);
            float t = h.x * Bh[i] + h.y * Bh[N + i]
                    + h.z * Bh[2 * N + i] + h.w * Bh[3 * N + i];
            g_scale[i] = s * SCALING;
            g_shift[i] = t * SCALING;
            __threadfence();
        }
        __syncthreads();
        if (tid == 0) atomicAdd(&g_done, 1u);
    }

    // ---- row LayerNorm ----
    const size_t row_off = (size_t)bid * (size_t)N;
    const float4* __restrict__ xr = (const float4*)(x + row_off);
    float4* __restrict__ orow = (float4*)(out + row_off);

    // Early gate probe (overlaps with everything below).
    unsigned done_early = *(volatile unsigned*)&g_done;

    float4 v[LN_ITER];
    float sum = 0.f, sq = 0.f;
#pragma unroll
    for (int it = 0; it < LN_ITER; it++) {
        v[it] = xr[tid + it * LN_T];
    }
#pragma unroll
    for (int it = 0; it < LN_ITER; it++) {
        float4 t = v[it];
        sum += t.x + t.y + t.z + t.w;
        sq  += t.x * t.x + t.y * t.y + t.z * t.z + t.w * t.w;
    }

    // Single-barrier block reduction across 16 warps.
    __shared__ float2 red[16];
#pragma unroll
    for (int o = 16; o > 0; o >>= 1) {
        sum += __shfl_xor_sync(0xffffffffu, sum, o);
        sq  += __shfl_xor_sync(0xffffffffu, sq, o);
    }
    const int warp = tid >> 5, lane = tid & 31;
    if (lane == 0) red[warp] = make_float2(sum, sq);
    __syncthreads();
    float ts = 0.f, tq = 0.f;
#pragma unroll
    for (int w = 0; w < 16; w++) {
        float2 p = red[w];              // broadcast, conflict-free
        ts += p.x;
        tq += p.y;
    }

    const float inv_n = 1.0f / (float)N;
    const float mean = ts * inv_n;
    const float var = fmaxf(tq * inv_n - mean * mean, 0.f);
    const float rstd = rsqrtf(var + EPS);

    // Gate: almost always already open (done_early from before the loads).
    if (done_early < (unsigned)PROD_BLOCKS) {
        while (*(volatile unsigned*)&g_done < (unsigned)PROD_BLOCKS) {}
        __threadfence();
    }

    const float4* __restrict__ sc4 = (const float4*)g_scale;
    const float4* __restrict__ sh4 = (const float4*)g_shift;
#pragma unroll
    for (int it = 0; it < LN_ITER; it++) {
        const int idx = tid + it * LN_T;
        float4 t = v[it];
        float4 sc = __ldg(&sc4[idx]);
        float4 sh = __ldg(&sh4[idx]);
        float4 o;
        o.x = (t.x - mean) * rstd * sc.x + sh.x;
        o.y = (t.y - mean) * rstd * sc.y + sh.y;
        o.z = (t.z - mean) * rstd * sc.z + sh.z;
        o.w = (t.w - mean) * rstd * sc.w + sh.w;
        orow[idx] = o;
    }
}

extern "C" void kernel_launch(void* const* d_in, const int* in_sizes, int n_in,
                              void* d_out, int out_size) {
    const float* x  = (const float*)d_in[0];
    const float* As = (const float*)d_in[1];
    const float* Bs = (const float*)d_in[2];
    const float* Ah = (const float*)d_in[3];
    const float* Bh = (const float*)d_in[4];
    float* out = (float*)d_out;

    const int N = in_sizes[2] / RANK;                          // 8192
    const int rows = (int)((size_t)in_sizes[0] / (size_t)N);   // 8192

    fused_kernel<<<rows, LN_T>>>(x, As, Bs, Ah, Bh, out, N);
}

// round 6
// speedup vs baseline: 1.1487x; 1.1487x over previous
#include <cuda_runtime.h>
#include <cuda_bf16.h>

// LoRALayerNorm: out = layernorm(x) * scale + shift
// R6: back to proven two-kernel R2 structure; bump to 3 CTAs/SM (48 warps =
// 100% occ on sm_103a, regs capped <=42 via launch_bounds) for better
// coverage of per-CTA barrier gaps. Vectorized lora side-kernel.

#define RANK 4
#define SCALING 2.0f   /* ALPHA(8) / RANK(4) */
#define EPS 1e-5f
#define MAX_N 8192

__device__ float g_scale[MAX_N];
__device__ float g_shift[MAX_N];

// Each thread computes 4 consecutive features: all loads are float4.
__global__ void lora_vec_kernel(const float* __restrict__ As,
                                const float* __restrict__ Bs,
                                const float* __restrict__ Ah,
                                const float* __restrict__ Bh,
                                int N) {
    const int i0 = (blockIdx.x * blockDim.x + threadIdx.x) * 4;
    if (i0 >= N) return;

    const float4* As4 = (const float4*)(As + i0 * RANK);   // 4 consecutive rows of A
    float4 b0 = *(const float4*)(Bs + 0 * N + i0);
    float4 b1 = *(const float4*)(Bs + 1 * N + i0);
    float4 b2 = *(const float4*)(Bs + 2 * N + i0);
    float4 b3 = *(const float4*)(Bs + 3 * N + i0);
    float4 a0 = As4[0], a1 = As4[1], a2 = As4[2], a3 = As4[3];
    float4 s;
    s.x = a0.x * b0.x + a0.y * b1.x + a0.z * b2.x + a0.w * b3.x;
    s.y = a1.x * b0.y + a1.y * b1.y + a1.z * b2.y + a1.w * b3.y;
    s.z = a2.x * b0.z + a2.y * b1.z + a2.z * b2.z + a2.w * b3.z;
    s.w = a3.x * b0.w + a3.y * b1.w + a3.z * b2.w + a3.w * b3.w;
    s.x *= SCALING; s.y *= SCALING; s.z *= SCALING; s.w *= SCALING;
    *(float4*)(g_scale + i0) = s;

    const float4* Ah4 = (const float4*)(Ah + i0 * RANK);
    float4 c0 = *(const float4*)(Bh + 0 * N + i0);
    float4 c1 = *(const float4*)(Bh + 1 * N + i0);
    float4 c2 = *(const float4*)(Bh + 2 * N + i0);
    float4 c3 = *(const float4*)(Bh + 3 * N + i0);
    float4 h0 = Ah4[0], h1 = Ah4[1], h2 = Ah4[2], h3 = Ah4[3];
    float4 t;
    t.x = h0.x * c0.x + h0.y * c1.x + h0.z * c2.x + h0.w * c3.x;
    t.y = h1.x * c0.y + h1.y * c1.y + h1.z * c2.y + h1.w * c3.y;
    t.z = h2.x * c0.z + h2.y * c1.z + h2.z * c2.z + h2.w * c3.z;
    t.w = h3.x * c0.w + h3.y * c1.w + h3.z * c2.w + h3.w * c3.w;
    t.x *= SCALING; t.y *= SCALING; t.z *= SCALING; t.w *= SCALING;
    *(float4*)(g_shift + i0) = t;
}

// One block per row. 512 threads, each owns 4 float4 = 16 floats of the row.
// 3 CTAs/SM (48 warps = full occupancy); launch_bounds caps regs at 42.
__global__ __launch_bounds__(512, 3)
void ln_kernel(const float* __restrict__ x, float* __restrict__ out, int N) {
    const int tid = threadIdx.x;
    const size_t row_off = (size_t)blockIdx.x * (size_t)N;
    const float4* __restrict__ xr = (const float4*)(x + row_off);
    float4* __restrict__ orow = (float4*)(out + row_off);

    float4 v[4];
    float sum = 0.f, sq = 0.f;
#pragma unroll
    for (int it = 0; it < 4; it++) {
        float4 t = xr[tid + it * 512];
        v[it] = t;
        sum += t.x + t.y + t.z + t.w;
        sq  += t.x * t.x + t.y * t.y + t.z * t.z + t.w * t.w;
    }

    __shared__ float red_s[16];
    __shared__ float red_q[16];
#pragma unroll
    for (int o = 16; o > 0; o >>= 1) {
        sum += __shfl_xor_sync(0xffffffffu, sum, o);
        sq  += __shfl_xor_sync(0xffffffffu, sq, o);
    }
    const int warp = tid >> 5, lane = tid & 31;
    if (lane == 0) { red_s[warp] = sum; red_q[warp] = sq; }
    __syncthreads();
    if (warp == 0) {
        float s = (lane < 16) ? red_s[lane] : 0.f;
        float q = (lane < 16) ? red_q[lane] : 0.f;
#pragma unroll
        for (int o = 8; o > 0; o >>= 1) {
            s += __shfl_xor_sync(0xffffffffu, s, o);
            q += __shfl_xor_sync(0xffffffffu, q, o);
        }
        if (lane == 0) { red_s[0] = s; red_q[0] = q; }
    }
    __syncthreads();

    const float inv_n = 1.0f / (float)N;
    const float mean = red_s[0] * inv_n;
    const float var = fmaxf(red_q[0] * inv_n - mean * mean, 0.f);
    const float rstd = rsqrtf(var + EPS);

    const float4* __restrict__ sc4 = (const float4*)g_scale;
    const float4* __restrict__ sh4 = (const float4*)g_shift;
#pragma unroll
    for (int it = 0; it < 4; it++) {
        const int idx = tid + it * 512;
        float4 t = v[it];
        float4 sc = __ldg(&sc4[idx]);
        float4 sh = __ldg(&sh4[idx]);
        float4 o;
        o.x = (t.x - mean) * rstd * sc.x + sh.x;
        o.y = (t.y - mean) * rstd * sc.y + sh.y;
        o.z = (t.z - mean) * rstd * sc.z + sh.z;
        o.w = (t.w - mean) * rstd * sc.w + sh.w;
        orow[idx] = o;
    }
}

extern "C" void kernel_launch(void* const* d_in, const int* in_sizes, int n_in,
                              void* d_out, int out_size) {
    const float* x  = (const float*)d_in[0];
    const float* As = (const float*)d_in[1];
    const float* Bs = (const float*)d_in[2];
    const float* Ah = (const float*)d_in[3];
    const float* Bh = (const float*)d_in[4];
    float* out = (float*)d_out;

    const int N = in_sizes[2] / RANK;                          // 8192
    const int rows = (int)((size_t)in_sizes[0] / (size_t)N);   // 8192

    lora_vec_kernel<<<N / (4 * 256), 256>>>(As, Bs, Ah, Bh, N);
    ln_kernel<<<rows, 512>>>(x, out, N);
}